// round 3
// baseline (speedup 1.0000x reference)
#include <cuda_runtime.h>
#include <cstdint>

#define BB 4096
#define NN 32
#define HH 128
#define LL 16
#define AA 10
#define HYBN 3
#define NE 62

// output layout: tuple flattened in return order, float32
#define NF_OFF    0
#define ALP_OFF   (BB*NN*17)              // 2228224
#define HLP_OFF   (ALP_OFF + BB)          // 2232320
#define EATTR_OFF (HLP_OFF + BB)          // 2236416
#define EMASK_OFF (EATTR_OFF + BB*NE*4)   // 3252224

// scratch (__device__ global: allocation-free)
__device__ float d_X[BB*HH];

__constant__ float c_maxval[AA] = {4.f,3.f,2.f,1.f,4.f,2.f,6.f,1.f,4.f,4.f};

// ---------------- Threefry-2x32 (exact JAX implementation) ----------------
__host__ __device__ __forceinline__ uint32_t rotl32(uint32_t x, int d) {
    return (x << d) | (x >> (32 - d));
}
__host__ __device__ __forceinline__ void threefry2x32(uint32_t k0, uint32_t k1,
                                                      uint32_t x0, uint32_t x1,
                                                      uint32_t& o0, uint32_t& o1) {
    uint32_t ks2 = k0 ^ k1 ^ 0x1BD11BDAu;
#define TFR(r) { x0 += x1; x1 = rotl32(x1, (r)); x1 ^= x0; }
    x0 += k0; x1 += k1;
    TFR(13) TFR(15) TFR(26) TFR(6)   x0 += k1;  x1 += ks2 + 1u;
    TFR(17) TFR(29) TFR(16) TFR(24)  x0 += ks2; x1 += k0 + 2u;
    TFR(13) TFR(15) TFR(26) TFR(6)   x0 += k0;  x1 += k1 + 3u;
    TFR(17) TFR(29) TFR(16) TFR(24)  x0 += k1;  x1 += ks2 + 4u;
    TFR(13) TFR(15) TFR(26) TFR(6)   x0 += ks2; x1 += k0 + 5u;
#undef TFR
    o0 = x0; o1 = x1;
}

// partitionable-mode 32-bit random bits: threefry(key,(0,idx)), xor-fold
__device__ __forceinline__ uint32_t rbits32(uint32_t k0, uint32_t k1, uint32_t idx) {
    uint32_t o0, o1;
    threefry2x32(k0, k1, 0u, idx, o0, o1);
    return o0 ^ o1;
}

__device__ __forceinline__ float bits_to_u01(uint32_t b) {
    return __uint_as_float((b >> 9) | 0x3f800000u) - 1.0f;
}

__device__ __forceinline__ float gumbel_draw(uint32_t k0, uint32_t k1, uint32_t idx,
                                             float mn, float span) {
    float u = bits_to_u01(rbits32(k0, k1, idx));
    u = fmaxf(mn, __fadd_rn(__fmul_rn(u, span), mn));
    return -logf(-logf(u));
}

// ---------------- MLP chain (node-uniform GAT stack collapsed to [B,H]) ----------------
// 512 threads: col = tid&127, row-group rh = tid>>7 (4 groups x 7 rows = 28 rows/block)
#define BROWS 28
__global__ void __launch_bounds__(512) mlp_kernel(
    const float* __restrict__ noise, const float* __restrict__ w1,
    const float* __restrict__ b1, const float* __restrict__ gw,
    const float* __restrict__ gb) {
    __shared__ float Ws[HH * HH];       // 64 KB
    __shared__ float xs[BROWS * HH];    // 14 KB
    const int tid = threadIdx.x;
    const int col = tid & 127;
    const int rh = tid >> 7;            // 0..3
    const int base = blockIdx.x * BROWS;

    // load input rows (noise)
    for (int i = tid; i < BROWS * HH; i += 512) {
        int r = i >> 7, g = base + r;
        xs[i] = (g < BB) ? noise[g * HH + (i & 127)] : 0.f;
    }

    for (int layer = 0; layer <= LL; layer++) {
        const float* Wsrc = (layer == 0) ? w1 : gw + (size_t)(layer - 1) * HH * HH;
        const float* bsrc = (layer == 0) ? b1 : gb + (layer - 1) * HH;
        {
            const float4* wv = (const float4*)Wsrc;
            float4* wd = (float4*)Ws;
            #pragma unroll
            for (int i = 0; i < 8; i++) wd[tid + i * 512] = wv[tid + i * 512];
        }
        __syncthreads();   // Ws ready, xs writes from previous layer ready

        float acc[7];
        const float bias = bsrc[col];
        #pragma unroll
        for (int r = 0; r < 7; r++) acc[r] = bias;
        const float* xrow = &xs[(rh * 7) * HH];
        #pragma unroll 4
        for (int k = 0; k < HH; k += 4) {
            float w0 = Ws[(k + 0) * HH + col];
            float w1v = Ws[(k + 1) * HH + col];
            float w2 = Ws[(k + 2) * HH + col];
            float w3 = Ws[(k + 3) * HH + col];
            #pragma unroll
            for (int r = 0; r < 7; r++) {
                const float4 xv = *(const float4*)&xrow[r * HH + k];
                acc[r] = fmaf(xv.x, w0, acc[r]);
                acc[r] = fmaf(xv.y, w1v, acc[r]);
                acc[r] = fmaf(xv.z, w2, acc[r]);
                acc[r] = fmaf(xv.w, w3, acc[r]);
            }
        }
        float res[7];
        #pragma unroll
        for (int r = 0; r < 7; r++) res[r] = xrow[r * HH + col];
        __syncthreads();   // all reads of xs/Ws complete
        #pragma unroll
        for (int r = 0; r < 7; r++) {
            float v = (layer == 0) ? acc[r] : acc[r] + res[r];
            xs[(rh * 7 + r) * HH + col] = fmaxf(v, 0.f);
        }
    }
    __syncthreads();
    #pragma unroll
    for (int r = 0; r < 7; r++) {
        int g = base + rh * 7 + r;
        if (g < BB) d_X[(size_t)g * HH + col] = xs[(rh * 7 + r) * HH + col];
    }
}

// ---------------- Heads: logits, inline sampling, node features, edges ----------------
__global__ void __launch_bounds__(64) heads_kernel(
    const float* __restrict__ w_atom, const float* __restrict__ b_atom,
    const float* __restrict__ w_hyb,  const float* __restrict__ b_hyb,
    const float* __restrict__ w_deg,  const float* __restrict__ b_deg,
    const float* __restrict__ w_chg,  const float* __restrict__ b_chg,
    const float* __restrict__ w_arom, const float* __restrict__ b_arom,
    const float* __restrict__ w_eex,  const float* __restrict__ b_eex,
    const float* __restrict__ w_ety,  const float* __restrict__ b_ety,
    uint32_t a_k0, uint32_t a_k1, uint32_t h_k0, uint32_t h_k1,
    uint32_t r_k0, uint32_t r_k1, uint32_t e_k0, uint32_t e_k1,
    float mn, float span,
    float* __restrict__ out) {
    const int b = blockIdx.x;
    const int tid = threadIdx.x;
    const int wid = tid >> 5;
    const int lane = tid & 31;
    __shared__ float xv[HH];
    __shared__ float alog[AA], alp[AA], hlog[HYBN], hlp[HYBN];
    __shared__ float sdeg, schg, sarom;
    __shared__ float nf[NN][18];
    __shared__ float wes[34], wts[136];
    __shared__ float wsum[4];

    xv[tid] = d_X[(size_t)b * HH + tid];
    xv[tid + 64] = d_X[(size_t)b * HH + tid + 64];
    if (tid < 34) wes[tid] = w_eex[tid];
    for (int i = tid; i < 136; i += 64) wts[i] = w_ety[i];
    __syncthreads();

    // ---- head dot products: 16 outputs x 4 threads, 32 k each ----
    {
        const int o = (wid << 3) | (lane >> 2);   // 0..15
        const int part = lane & 3;
        const float* wp; int stride;
        if (o < AA)       { wp = w_atom + o;        stride = AA; }
        else if (o < 13)  { wp = w_hyb + (o - 10);  stride = HYBN; }
        else if (o == 13) { wp = w_deg;             stride = 1; }
        else if (o == 14) { wp = w_chg;             stride = 1; }
        else              { wp = w_arom;            stride = 1; }
        float acc = 0.f;
        const int k0 = part * 32;
        #pragma unroll 8
        for (int k = 0; k < 32; k++)
            acc = fmaf(xv[k0 + k], wp[(k0 + k) * stride], acc);
        acc += __shfl_down_sync(0xffffffffu, acc, 2);
        acc += __shfl_down_sync(0xffffffffu, acc, 1);
        if (part == 0) {
            if (o < AA)       alog[o] = acc + b_atom[o];
            else if (o < 13)  hlog[o - 10] = acc + b_hyb[o - 10];
            else if (o == 13) sdeg = 1.f / (1.f + expf(-(acc + b_deg[0])));
            else if (o == 14) schg = tanhf(acc + b_chg[0]);
            else              sarom = 1.f / (1.f + expf(-(acc + b_arom[0])));
        }
    }
    __syncthreads();

    // ---- log-softmax (warp 0, lane-parallel) ----
    if (wid == 0) {
        float v = (lane < AA) ? alog[lane] : -3.4e38f;
        float m = v;
        #pragma unroll
        for (int off = 16; off > 0; off >>= 1)
            m = fmaxf(m, __shfl_xor_sync(0xffffffffu, m, off));
        float e = (lane < AA) ? expf(alog[lane] - m) : 0.f;
        float s = e;
        #pragma unroll
        for (int off = 16; off > 0; off >>= 1)
            s += __shfl_xor_sync(0xffffffffu, s, off);
        float lse = logf(s);
        if (lane < AA) alp[lane] = alog[lane] - m - lse;

        float v2 = (lane < HYBN) ? hlog[lane] : -3.4e38f;
        float m2 = v2;
        #pragma unroll
        for (int off = 16; off > 0; off >>= 1)
            m2 = fmaxf(m2, __shfl_xor_sync(0xffffffffu, m2, off));
        float e2 = (lane < HYBN) ? expf(hlog[lane] - m2) : 0.f;
        float s2 = e2;
        #pragma unroll
        for (int off = 16; off > 0; off >>= 1)
            s2 += __shfl_xor_sync(0xffffffffu, s2, off);
        float lse2 = logf(s2);
        if (lane < HYBN) hlp[lane] = hlog[lane] - m2 - lse2;
    }
    __syncthreads();

    // ---- node phase: 2 threads per node ----
    float myalp = 0.f, myhlp = 0.f;
    {
        const int n = tid >> 1;
        const int h = tid & 1;
        const uint32_t node = (uint32_t)(b * NN + n);

        // atom: h handles categories h*5 .. h*5+4
        int ai = h * 5;
        float best = -3.4e38f;
        #pragma unroll
        for (int j = 0; j < 5; j++) {
            int a = h * 5 + j;
            float g = gumbel_draw(a_k0, a_k1, node * AA + a, mn, span);
            float v = alog[a] + g;
            if (v > best) { best = v; ai = a; }
        }
        {
            float ob = __shfl_xor_sync(0xffffffffu, best, 1);
            int   oi = __shfl_xor_sync(0xffffffffu, ai, 1);
            if (ob > best || (ob == best && oi < ai)) { best = ob; ai = oi; }
        }
        // hyb: h==0 -> {0,1}, h==1 -> {2}
        int hi = (h == 0) ? 0 : 2;
        float bh = -3.4e38f;
        if (h == 0) {
            #pragma unroll
            for (int a = 0; a < 2; a++) {
                float g = gumbel_draw(h_k0, h_k1, node * HYBN + a, mn, span);
                float v = hlog[a] + g;
                if (v > bh) { bh = v; hi = a; }
            }
        } else {
            float g = gumbel_draw(h_k0, h_k1, node * HYBN + 2, mn, span);
            bh = hlog[2] + g;
        }
        {
            float ob = __shfl_xor_sync(0xffffffffu, bh, 1);
            int   oi = __shfl_xor_sync(0xffffffffu, hi, 1);
            if (ob > bh || (ob == bh && oi < hi)) { bh = ob; hi = oi; }
        }
        // arom uniform: computed by h==1, swapped to h==0
        float u = 0.f;
        if (h == 1) u = bits_to_u01(rbits32(r_k0, r_k1, node));
        u = __shfl_xor_sync(0xffffffffu, u, 1);   // h==0 now has it

        if (h == 0) {
            float arom = (u < sarom) ? 1.f : 0.f;
            float val = c_maxval[ai] / 5.0f;
            float* o = out + NF_OFF + (size_t)node * 17;
            #pragma unroll
            for (int f = 0; f < AA; f++) { float x = (f == ai) ? 1.f : 0.f; nf[n][f] = x; o[f] = x; }
            nf[n][10] = sdeg;  o[10] = sdeg;
            nf[n][11] = schg;  o[11] = schg;
            #pragma unroll
            for (int f = 0; f < HYBN; f++) { float x = (f == hi) ? 1.f : 0.f; nf[n][12 + f] = x; o[12 + f] = x; }
            nf[n][15] = arom;  o[15] = arom;
            nf[n][16] = val;   o[16] = val;
            myalp = alp[ai];
            myhlp = hlp[hi];
        }
    }
    // reduce lp means (contributions on even tids only)
    #pragma unroll
    for (int off = 16; off > 0; off >>= 1) {
        myalp += __shfl_down_sync(0xffffffffu, myalp, off);
        myhlp += __shfl_down_sync(0xffffffffu, myhlp, off);
    }
    if (lane == 0) { wsum[wid] = myalp; wsum[2 + wid] = myhlp; }
    __syncthreads();
    if (tid == 0) {
        out[ALP_OFF + b] = (wsum[0] + wsum[1]) / 32.f;
        out[HLP_OFF + b] = (wsum[2] + wsum[3]) / 32.f;
    }

    // ---- edge phase (threads 0..61) ----
    if (tid < NE) {
        const int e = tid;
        const int un = (e < 31) ? e : e - 30;       // eu
        const int vn = (e < 31) ? e + 1 : e - 31;   // ev
        float elog = b_eex[0];
        float tl[4];
        #pragma unroll
        for (int t = 0; t < 4; t++) tl[t] = b_ety[t];
        #pragma unroll
        for (int f = 0; f < 17; f++) {
            float a1 = nf[un][f];
            float a2 = nf[vn][f];
            elog = fmaf(a1, wes[f], elog);
            elog = fmaf(a2, wes[17 + f], elog);
            #pragma unroll
            for (int t = 0; t < 4; t++) {
                tl[t] = fmaf(a1, wts[f * 4 + t], tl[t]);
                tl[t] = fmaf(a2, wts[(17 + f) * 4 + t], tl[t]);
            }
        }
        float p = 1.f / (1.f + expf(-elog));
        out[EMASK_OFF + (size_t)b * NE + e] = (p > 0.5f) ? 1.f : 0.f;

        const uint32_t ebase = (uint32_t)(b * NE + e) * 4u;
        int ti = 0; float bt = -1e30f;
        #pragma unroll
        for (int t = 0; t < 4; t++) {
            float g = gumbel_draw(e_k0, e_k1, ebase + t, mn, span);
            float v = tl[t] + g;
            if (v > bt) { bt = v; ti = t; }
        }
        float* oe = out + EATTR_OFF + (size_t)ebase;
        #pragma unroll
        for (int t = 0; t < 4; t++) oe[t] = (t == ti) ? 1.f : 0.f;
    }
}

// ---------------- launch ----------------
extern "C" void kernel_launch(void* const* d_in, const int* in_sizes, int n_in,
                              void* d_out, int out_size) {
    const float* noise  = (const float*)d_in[0];
    const float* w1     = (const float*)d_in[1];
    const float* b1     = (const float*)d_in[2];
    const float* gat_w  = (const float*)d_in[3];
    const float* gat_b  = (const float*)d_in[4];
    // d_in[5] att_src, d_in[6] att_dst: numerically irrelevant (node-uniform collapse)
    const float* w_atom = (const float*)d_in[7];
    const float* b_atom = (const float*)d_in[8];
    const float* w_hyb  = (const float*)d_in[9];
    const float* b_hyb  = (const float*)d_in[10];
    const float* w_deg  = (const float*)d_in[11];
    const float* b_deg  = (const float*)d_in[12];
    const float* w_chg  = (const float*)d_in[13];
    const float* b_chg  = (const float*)d_in[14];
    const float* w_arom = (const float*)d_in[15];
    const float* b_arom = (const float*)d_in[16];
    const float* w_eex  = (const float*)d_in[17];
    const float* b_eex  = (const float*)d_in[18];
    const float* w_ety  = (const float*)d_in[19];
    const float* b_ety  = (const float*)d_in[20];
    float* out = (float*)d_out;

    // jax.random.key(42) -> (0, 42); partitionable split: sk[i] = threefry(key,(0,i))
    uint32_t sk[4][2];
    for (uint32_t i = 0; i < 4; i++)
        threefry2x32(0u, 42u, 0u, i, sk[i][0], sk[i][1]);

    const float mn = 1e-6f;
    const float mx = (float)(1.0 - 1e-6);
    const float span = mx - mn;

    mlp_kernel<<<(BB + BROWS - 1) / BROWS, 512>>>(noise, w1, b1, gat_w, gat_b);

    heads_kernel<<<BB, 64>>>(w_atom, b_atom, w_hyb, b_hyb, w_deg, b_deg,
                             w_chg, b_chg, w_arom, b_arom, w_eex, b_eex,
                             w_ety, b_ety,
                             sk[0][0], sk[0][1], sk[1][0], sk[1][1],
                             sk[2][0], sk[2][1], sk[3][0], sk[3][1],
                             mn, span, out);
}

// round 5
// speedup vs baseline: 1.4541x; 1.4541x over previous
#include <cuda_runtime.h>
#include <cstdint>

#define BB 4096
#define NN 32
#define HH 128
#define LL 16
#define AA 10
#define HYBN 3
#define NE 62

// output layout: tuple flattened in return order, float32
#define NF_OFF    0
#define ALP_OFF   (BB*NN*17)              // 2228224
#define HLP_OFF   (ALP_OFF + BB)          // 2232320
#define EATTR_OFF (HLP_OFF + BB)          // 2236416
#define EMASK_OFF (EATTR_OFF + BB*NE*4)   // 3252224

// scratch (__device__ global: allocation-free)
__device__ __align__(16) float d_X[BB*HH];

__constant__ float c_maxval[AA] = {4.f,3.f,2.f,1.f,4.f,2.f,6.f,1.f,4.f,4.f};

// ---------------- Threefry-2x32 (exact JAX implementation) ----------------
__host__ __device__ __forceinline__ uint32_t rotl32(uint32_t x, int d) {
    return (x << d) | (x >> (32 - d));
}
__host__ __device__ __forceinline__ void threefry2x32(uint32_t k0, uint32_t k1,
                                                      uint32_t x0, uint32_t x1,
                                                      uint32_t& o0, uint32_t& o1) {
    uint32_t ks2 = k0 ^ k1 ^ 0x1BD11BDAu;
#define TFR(r) { x0 += x1; x1 = rotl32(x1, (r)); x1 ^= x0; }
    x0 += k0; x1 += k1;
    TFR(13) TFR(15) TFR(26) TFR(6)   x0 += k1;  x1 += ks2 + 1u;
    TFR(17) TFR(29) TFR(16) TFR(24)  x0 += ks2; x1 += k0 + 2u;
    TFR(13) TFR(15) TFR(26) TFR(6)   x0 += k0;  x1 += k1 + 3u;
    TFR(17) TFR(29) TFR(16) TFR(24)  x0 += k1;  x1 += ks2 + 4u;
    TFR(13) TFR(15) TFR(26) TFR(6)   x0 += ks2; x1 += k0 + 5u;
#undef TFR
    o0 = x0; o1 = x1;
}

// partitionable-mode 32-bit random bits: threefry(key,(0,idx)), xor-fold
__device__ __forceinline__ uint32_t rbits32(uint32_t k0, uint32_t k1, uint32_t idx) {
    uint32_t o0, o1;
    threefry2x32(k0, k1, 0u, idx, o0, o1);
    return o0 ^ o1;
}

__device__ __forceinline__ float bits_to_u01(uint32_t b) {
    return __uint_as_float((b >> 9) | 0x3f800000u) - 1.0f;
}

__device__ __forceinline__ float gumbel_draw(uint32_t k0, uint32_t k1, uint32_t idx,
                                             float mn, float span) {
    float u = bits_to_u01(rbits32(k0, k1, idx));
    u = fmaxf(mn, __fadd_rn(__fmul_rn(u, span), mn));
    return -logf(-logf(u));
}

// ---------------- MLP chain (node-uniform GAT stack collapsed to [B,H]) ----------------
// 256 threads, 14 rows/block, 2 blocks/SM. col = tid&127, rh = tid>>7 (7 rows each).
#define BROWS 14
__global__ void __launch_bounds__(256, 2) mlp_kernel(
    const float* __restrict__ noise, const float* __restrict__ w1,
    const float* __restrict__ b1, const float* __restrict__ gw,
    const float* __restrict__ gb) {
    __shared__ __align__(16) float Ws[HH * HH];       // 64 KB
    __shared__ __align__(16) float xs[BROWS * HH];    // 7 KB
    const int tid = threadIdx.x;
    const int col = tid & 127;
    const int rh = tid >> 7;            // 0 or 1
    const int base = blockIdx.x * BROWS;

    // load input rows (noise)
    for (int i = tid; i < BROWS * HH; i += 256) {
        int r = i >> 7, g = base + r;
        xs[i] = (g < BB) ? noise[g * HH + (i & 127)] : 0.f;
    }

    float keep[7];                       // residual carried in registers
    for (int layer = 0; layer <= LL; layer++) {
        const float* Wsrc = (layer == 0) ? w1 : gw + (size_t)(layer - 1) * HH * HH;
        const float* bsrc = (layer == 0) ? b1 : gb + (layer - 1) * HH;
        {
            const float4* wv = (const float4*)Wsrc;
            float4* wd = (float4*)Ws;
            #pragma unroll
            for (int i = 0; i < 16; i++) wd[tid + i * 256] = wv[tid + i * 256];
        }
        __syncthreads();   // Ws ready; xs stores from previous layer done

        float acc[7];
        const float bias = bsrc[col];
        #pragma unroll
        for (int r = 0; r < 7; r++) acc[r] = bias;
        const float* xrow = &xs[(rh * 7) * HH];
        #pragma unroll 2
        for (int k = 0; k < HH; k += 4) {
            float w0 = Ws[(k + 0) * HH + col];
            float w1v = Ws[(k + 1) * HH + col];
            float w2 = Ws[(k + 2) * HH + col];
            float w3 = Ws[(k + 3) * HH + col];
            #pragma unroll
            for (int r = 0; r < 7; r++) {
                const float4 xv = *(const float4*)&xrow[r * HH + k];
                acc[r] = fmaf(xv.x, w0, acc[r]);
                acc[r] = fmaf(xv.y, w1v, acc[r]);
                acc[r] = fmaf(xv.z, w2, acc[r]);
                acc[r] = fmaf(xv.w, w3, acc[r]);
            }
        }
        __syncthreads();   // all reads of xs/Ws complete
        #pragma unroll
        for (int r = 0; r < 7; r++) {
            float v = (layer == 0) ? acc[r] : acc[r] + keep[r];
            v = fmaxf(v, 0.f);
            keep[r] = v;
            xs[(rh * 7 + r) * HH + col] = v;
        }
    }
    #pragma unroll
    for (int r = 0; r < 7; r++) {
        int g = base + rh * 7 + r;
        if (g < BB) d_X[(size_t)g * HH + col] = keep[r];
    }
}

// ---------------- Heads: warp-per-batch (8 batches / 256-thread block) ----------------
__global__ void __launch_bounds__(256) heads_kernel(
    const float* __restrict__ w_atom, const float* __restrict__ b_atom,
    const float* __restrict__ w_hyb,  const float* __restrict__ b_hyb,
    const float* __restrict__ w_deg,  const float* __restrict__ b_deg,
    const float* __restrict__ w_chg,  const float* __restrict__ b_chg,
    const float* __restrict__ w_arom, const float* __restrict__ b_arom,
    const float* __restrict__ w_eex,  const float* __restrict__ b_eex,
    const float* __restrict__ w_ety,  const float* __restrict__ b_ety,
    uint32_t a_k0, uint32_t a_k1, uint32_t h_k0, uint32_t h_k1,
    uint32_t r_k0, uint32_t r_k1, uint32_t e_k0, uint32_t e_k1,
    float mn, float span,
    float* __restrict__ out) {
    __shared__ __align__(16) float xvs[8][HH];   // float4-accessed: declare first, aligned
    __shared__ __align__(16) float wa[HH * AA];
    __shared__ __align__(16) float wh[HH * HYBN];
    __shared__ __align__(16) float wdg[HH], wcg[HH], wrg[HH];
    __shared__ __align__(16) float wts[136];
    __shared__ __align__(16) float wes[34];
    __shared__ float nfs[8][NN][17];

    const int tid = threadIdx.x;
    const int wid = tid >> 5;
    const int lane = tid & 31;

    for (int i = tid; i < HH * AA; i += 256) wa[i] = w_atom[i];
    for (int i = tid; i < HH * HYBN; i += 256) wh[i] = w_hyb[i];
    if (tid < HH) { wdg[tid] = w_deg[tid]; wcg[tid] = w_chg[tid]; wrg[tid] = w_arom[tid]; }
    if (tid < 34) wes[tid] = w_eex[tid];
    if (tid >= 64 && tid < 200) wts[tid - 64] = w_ety[tid - 64];
    __syncthreads();

    const int b = blockIdx.x * 8 + wid;

    // load x row for this batch (d_X 16-aligned, b*HH*4 is 512B multiple)
    ((float4*)xvs[wid])[lane] = ((const float4*)(d_X + (size_t)b * HH))[lane];
    __syncwarp();

    // ---- dots: 16 outputs x 2 lanes, 64 k each ----
    const int o = lane >> 1;
    const int part = lane & 1;
    const float* wp; int stride; float bias;
    if (o < AA)       { wp = wa + o;        stride = AA;   bias = b_atom[o]; }
    else if (o < 13)  { wp = wh + (o - 10); stride = HYBN; bias = b_hyb[o - 10]; }
    else if (o == 13) { wp = wdg;           stride = 1;    bias = b_deg[0]; }
    else if (o == 14) { wp = wcg;           stride = 1;    bias = b_chg[0]; }
    else              { wp = wrg;           stride = 1;    bias = b_arom[0]; }
    float acc = 0.f;
    {
        const int k0 = part * 64;
        const float* xp = xvs[wid];
        #pragma unroll 8
        for (int k = 0; k < 64; k++)
            acc = fmaf(xp[k0 + k], wp[(k0 + k) * stride], acc);
    }
    acc += __shfl_xor_sync(0xffffffffu, acc, 1);
    const float logit = acc + bias;

    // ---- gather all logits to every lane ----
    float alog[AA], hlog[HYBN];
    #pragma unroll
    for (int a = 0; a < AA; a++) alog[a] = __shfl_sync(0xffffffffu, logit, 2 * a);
    #pragma unroll
    for (int a = 0; a < HYBN; a++) hlog[a] = __shfl_sync(0xffffffffu, logit, 20 + 2 * a);
    const float dlg = __shfl_sync(0xffffffffu, logit, 26);
    const float clg = __shfl_sync(0xffffffffu, logit, 28);
    const float rlg = __shfl_sync(0xffffffffu, logit, 30);
    const float sdeg = 1.f / (1.f + expf(-dlg));
    const float schg = tanhf(clg);
    const float sarom = 1.f / (1.f + expf(-rlg));

    // ---- log-softmax constants (redundant per lane, same serial order as R2) ----
    float m = alog[0];
    #pragma unroll
    for (int a = 1; a < AA; a++) m = fmaxf(m, alog[a]);
    float s = 0.f;
    #pragma unroll
    for (int a = 0; a < AA; a++) s += expf(alog[a] - m);
    const float malse_a = m + logf(s);
    float m2 = hlog[0];
    #pragma unroll
    for (int a = 1; a < HYBN; a++) m2 = fmaxf(m2, hlog[a]);
    float s2 = 0.f;
    #pragma unroll
    for (int a = 0; a < HYBN; a++) s2 += expf(hlog[a] - m2);
    const float malse_h = m2 + logf(s2);

    // ---- node phase: one node per lane ----
    const uint32_t node = (uint32_t)(b * NN + lane);
    int ai = 0; float best = -3.4e38f, alsel = 0.f;
    #pragma unroll
    for (int a = 0; a < AA; a++) {
        float g = gumbel_draw(a_k0, a_k1, node * AA + a, mn, span);
        float v = alog[a] + g;
        if (v > best) { best = v; ai = a; alsel = alog[a]; }
    }
    int hi = 0; float bh = -3.4e38f, hlsel = 0.f;
    #pragma unroll
    for (int a = 0; a < HYBN; a++) {
        float g = gumbel_draw(h_k0, h_k1, node * HYBN + a, mn, span);
        float v = hlog[a] + g;
        if (v > bh) { bh = v; hi = a; hlsel = hlog[a]; }
    }
    const float u = bits_to_u01(rbits32(r_k0, r_k1, node));
    const float arom = (u < sarom) ? 1.f : 0.f;
    const float val = c_maxval[ai] / 5.0f;
    {
        float* op = out + NF_OFF + (size_t)node * 17;
        #pragma unroll
        for (int f = 0; f < AA; f++) {
            float x = (f == ai) ? 1.f : 0.f;
            nfs[wid][lane][f] = x; op[f] = x;
        }
        nfs[wid][lane][10] = sdeg;  op[10] = sdeg;
        nfs[wid][lane][11] = schg;  op[11] = schg;
        #pragma unroll
        for (int f = 0; f < HYBN; f++) {
            float x = (f == hi) ? 1.f : 0.f;
            nfs[wid][lane][12 + f] = x; op[12 + f] = x;
        }
        nfs[wid][lane][15] = arom;  op[15] = arom;
        nfs[wid][lane][16] = val;   op[16] = val;
    }

    // ---- lp means (warp reduce) ----
    float myalp = alsel - malse_a;
    float myhlp = hlsel - malse_h;
    #pragma unroll
    for (int off = 16; off > 0; off >>= 1) {
        myalp += __shfl_down_sync(0xffffffffu, myalp, off);
        myhlp += __shfl_down_sync(0xffffffffu, myhlp, off);
    }
    if (lane == 0) {
        out[ALP_OFF + b] = myalp / 32.f;
        out[HLP_OFF + b] = myhlp / 32.f;
    }
    __syncwarp();

    // ---- edge phase: 2 edges per lane ----
    #pragma unroll
    for (int rep = 0; rep < 2; rep++) {
        const int e = lane + rep * 32;
        if (e < NE) {
            const int un = (e < 31) ? e : e - 30;       // eu
            const int vn = (e < 31) ? e + 1 : e - 31;   // ev
            float elog = b_eex[0];
            float tl[4];
            #pragma unroll
            for (int t = 0; t < 4; t++) tl[t] = b_ety[t];
            #pragma unroll
            for (int f = 0; f < 17; f++) {
                float a1 = nfs[wid][un][f];
                float a2 = nfs[wid][vn][f];
                elog = fmaf(a1, wes[f], elog);
                elog = fmaf(a2, wes[17 + f], elog);
                #pragma unroll
                for (int t = 0; t < 4; t++) {
                    tl[t] = fmaf(a1, wts[f * 4 + t], tl[t]);
                    tl[t] = fmaf(a2, wts[(17 + f) * 4 + t], tl[t]);
                }
            }
            float p = 1.f / (1.f + expf(-elog));
            out[EMASK_OFF + (size_t)b * NE + e] = (p > 0.5f) ? 1.f : 0.f;

            const uint32_t ebase = (uint32_t)(b * NE + e) * 4u;
            int ti = 0; float bt = -1e30f;
            #pragma unroll
            for (int t = 0; t < 4; t++) {
                float g = gumbel_draw(e_k0, e_k1, ebase + t, mn, span);
                float v = tl[t] + g;
                if (v > bt) { bt = v; ti = t; }
            }
            float4 oh;
            oh.x = (ti == 0) ? 1.f : 0.f;
            oh.y = (ti == 1) ? 1.f : 0.f;
            oh.z = (ti == 2) ? 1.f : 0.f;
            oh.w = (ti == 3) ? 1.f : 0.f;
            *(float4*)(out + EATTR_OFF + (size_t)ebase) = oh;
        }
    }
}

// ---------------- launch ----------------
extern "C" void kernel_launch(void* const* d_in, const int* in_sizes, int n_in,
                              void* d_out, int out_size) {
    const float* noise  = (const float*)d_in[0];
    const float* w1     = (const float*)d_in[1];
    const float* b1     = (const float*)d_in[2];
    const float* gat_w  = (const float*)d_in[3];
    const float* gat_b  = (const float*)d_in[4];
    // d_in[5] att_src, d_in[6] att_dst: numerically irrelevant (node-uniform collapse)
    const float* w_atom = (const float*)d_in[7];
    const float* b_atom = (const float*)d_in[8];
    const float* w_hyb  = (const float*)d_in[9];
    const float* b_hyb  = (const float*)d_in[10];
    const float* w_deg  = (const float*)d_in[11];
    const float* b_deg  = (const float*)d_in[12];
    const float* w_chg  = (const float*)d_in[13];
    const float* b_chg  = (const float*)d_in[14];
    const float* w_arom = (const float*)d_in[15];
    const float* b_arom = (const float*)d_in[16];
    const float* w_eex  = (const float*)d_in[17];
    const float* b_eex  = (const float*)d_in[18];
    const float* w_ety  = (const float*)d_in[19];
    const float* b_ety  = (const float*)d_in[20];
    float* out = (float*)d_out;

    // jax.random.key(42) -> (0, 42); partitionable split: sk[i] = threefry(key,(0,i))
    uint32_t sk[4][2];
    for (uint32_t i = 0; i < 4; i++)
        threefry2x32(0u, 42u, 0u, i, sk[i][0], sk[i][1]);

    const float mn = 1e-6f;
    const float mx = (float)(1.0 - 1e-6);
    const float span = mx - mn;

    mlp_kernel<<<(BB + BROWS - 1) / BROWS, 256>>>(noise, w1, b1, gat_w, gat_b);

    heads_kernel<<<BB / 8, 256>>>(w_atom, b_atom, w_hyb, b_hyb, w_deg, b_deg,
                                  w_chg, b_chg, w_arom, b_arom, w_eex, b_eex,
                                  w_ety, b_ety,
                                  sk[0][0], sk[0][1], sk[1][0], sk[1][1],
                                  sk[2][0], sk[2][1], sk[3][0], sk[3][1],
                                  mn, span, out);
}